// round 8
// baseline (speedup 1.0000x reference)
#include <cuda_runtime.h>
#include <cuda_bf16.h>
#include <math.h>

#define N_NODES  1000000
#define N_EDGES  16000000
#define N_GRAPHS 1024
#define SCAN_BLOCKS 977          // ceil(1e6 / 1024)

// ---------------- scratch (device globals: allocation-free) ----------------
__device__ __align__(16) float4 g_x1[2000000];     // x1: 1M x 8 fp32 (32 MB)
__device__ __align__(16) float4 g_x2[1000000];     // x2: 1M x 4 fp32 (16 MB)
__device__ __align__(16) int    g_deg_out[N_NODES];
__device__ __align__(16) int    g_deg_in[N_NODES];
__device__ __align__(16) int    g_offs[N_NODES];   // CSR row starts (by dst)
__device__ __align__(16) int    g_cursor[N_NODES]; // mutable copy for permute
__device__ int    g_blocksums[1024];
__device__ int    g_sorted_src[N_EDGES];           // src ids grouped by dst (64 MB)
__device__ float  g_gsum[N_GRAPHS * 4];
__device__ float  g_gcnt[N_GRAPHS];

// ---------------- kernels ----------------

__global__ void k_zero() {
    int i = blockIdx.x * blockDim.x + threadIdx.x;
    if (i < N_NODES / 4) { ((int4*)g_deg_out)[i] = make_int4(0,0,0,0);
                           ((int4*)g_deg_in)[i]  = make_int4(0,0,0,0); }
    if (i < N_GRAPHS) { ((float4*)g_gsum)[i] = make_float4(0.f,0.f,0.f,0.f);
                        g_gcnt[i] = 0.f; }
}

__global__ void k_degrees(const int* __restrict__ src, const int* __restrict__ dst) {
    int i = blockIdx.x * blockDim.x + threadIdx.x;
    if (i >= N_EDGES / 4) return;
    int4 s = ((const int4*)src)[i];
    int4 d = ((const int4*)dst)[i];
    atomicAdd(&g_deg_out[s.x], 1); atomicAdd(&g_deg_out[s.y], 1);
    atomicAdd(&g_deg_out[s.z], 1); atomicAdd(&g_deg_out[s.w], 1);
    atomicAdd(&g_deg_in[d.x], 1);  atomicAdd(&g_deg_in[d.y], 1);
    atomicAdd(&g_deg_in[d.z], 1);  atomicAdd(&g_deg_in[d.w], 1);
}

// ---- exclusive scan of deg_in -> offs ----
__global__ void k_scanA() {
    __shared__ int sh[256];
    int bid = blockIdx.x, t = threadIdx.x;
    int base = bid * 1024 + t * 4;
    int4 v = make_int4(0,0,0,0);
    if (base + 3 < N_NODES) v = *(const int4*)&g_deg_in[base];
    else {
        if (base + 0 < N_NODES) v.x = g_deg_in[base + 0];
        if (base + 1 < N_NODES) v.y = g_deg_in[base + 1];
        if (base + 2 < N_NODES) v.z = g_deg_in[base + 2];
        if (base + 3 < N_NODES) v.w = g_deg_in[base + 3];
    }
    int s0 = v.x, s1 = s0 + v.y, s2 = s1 + v.z, s3 = s2 + v.w;
    sh[t] = s3;
    __syncthreads();
    for (int off = 1; off < 256; off <<= 1) {
        int val = (t >= off) ? sh[t - off] : 0;
        __syncthreads();
        sh[t] += val;
        __syncthreads();
    }
    int excl = (t > 0) ? sh[t - 1] : 0;
    if (t == 255) g_blocksums[bid] = sh[255];
    int4 o = make_int4(excl, excl + s0, excl + s1, excl + s2);
    if (base + 3 < N_NODES) *(int4*)&g_offs[base] = o;
    else {
        if (base + 0 < N_NODES) g_offs[base + 0] = o.x;
        if (base + 1 < N_NODES) g_offs[base + 1] = o.y;
        if (base + 2 < N_NODES) g_offs[base + 2] = o.z;
        if (base + 3 < N_NODES) g_offs[base + 3] = o.w;
    }
}

__global__ void k_scanB() {
    __shared__ int sh[1024];
    int t = threadIdx.x;
    sh[t] = (t < SCAN_BLOCKS) ? g_blocksums[t] : 0;
    __syncthreads();
    for (int off = 1; off < 1024; off <<= 1) {
        int val = (t >= off) ? sh[t - off] : 0;
        __syncthreads();
        sh[t] += val;
        __syncthreads();
    }
    g_blocksums[t] = (t > 0) ? sh[t - 1] : 0;
}

__global__ void k_scanC() {
    int bid = blockIdx.x, t = threadIdx.x;
    int base = bid * 1024 + t * 4;
    int add = g_blocksums[bid];
    if (base + 3 < N_NODES) {
        int4 o = *(const int4*)&g_offs[base];
        o.x += add; o.y += add; o.z += add; o.w += add;
        *(int4*)&g_offs[base]   = o;
        *(int4*)&g_cursor[base] = o;
    } else {
        for (int k = 0; k < 4; k++)
            if (base + k < N_NODES) {
                int o = g_offs[base + k] + add;
                g_offs[base + k] = o; g_cursor[base + k] = o;
            }
    }
}

__global__ void k_permute(const int* __restrict__ src, const int* __restrict__ dst) {
    int i = blockIdx.x * blockDim.x + threadIdx.x;
    if (i >= N_EDGES / 4) return;
    int4 s = ((const int4*)src)[i];
    int4 d = ((const int4*)dst)[i];
    int p;
    p = atomicAdd(&g_cursor[d.x], 1); g_sorted_src[p] = s.x;
    p = atomicAdd(&g_cursor[d.y], 1); g_sorted_src[p] = s.y;
    p = atomicAdd(&g_cursor[d.z], 1); g_sorted_src[p] = s.z;
    p = atomicAdd(&g_cursor[d.w], 1); g_sorted_src[p] = s.w;
}

// x1 = (features * out_norm) @ W1
__global__ void k_proj1(const float* __restrict__ feat, const float* __restrict__ W1) {
    __shared__ float sW[80];
    if (threadIdx.x < 80) sW[threadIdx.x] = W1[threadIdx.x];
    __syncthreads();
    int n = blockIdx.x * blockDim.x + threadIdx.x;
    if (n >= N_NODES) return;
    float onorm = rsqrtf(fmaxf((float)g_deg_out[n], 1.f));
    const float2* fp = (const float2*)(feat + (size_t)n * 10);
    float f[10];
#pragma unroll
    for (int i = 0; i < 5; i++) { float2 v = fp[i]; f[2*i] = v.x * onorm; f[2*i+1] = v.y * onorm; }
    float o[8];
#pragma unroll
    for (int j = 0; j < 8; j++) o[j] = 0.f;
#pragma unroll
    for (int i = 0; i < 10; i++)
#pragma unroll
        for (int j = 0; j < 8; j++) o[j] += f[i] * sW[i * 8 + j];
    g_x1[n * 2]     = make_float4(o[0], o[1], o[2], o[3]);
    g_x1[n * 2 + 1] = make_float4(o[4], o[5], o[6], o[7]);
}

// gather layer 1: 8 threads per node, thread j owns feature j.
// Per edge: one broadcast index load + one coalesced 32B row load.
// Epilogue: relu + @W2 via intra-group shuffles. Grid exact: 31250*256 = 8M.
__global__ void k_gather1(const float* __restrict__ W2, const float* __restrict__ b1) {
    __shared__ float sW[32], sb[8];
    if (threadIdx.x < 32) sW[threadIdx.x] = W2[threadIdx.x];
    if (threadIdx.x < 8)  sb[threadIdx.x] = b1[threadIdx.x];
    __syncthreads();
    int t = threadIdx.x;
    int lane = t & 7;                                   // feature index
    int n = (blockIdx.x * blockDim.x + t) >> 3;         // node
    int start = __ldg(&g_offs[n]);
    int cnt   = __ldg(&g_deg_in[n]);
    const float* x1f = (const float*)g_x1;
    float acc = 0.f;
    int i = 0;
    for (; i + 3 < cnt; i += 4) {
        int s0 = __ldg(g_sorted_src + start + i);
        int s1 = __ldg(g_sorted_src + start + i + 1);
        int s2 = __ldg(g_sorted_src + start + i + 2);
        int s3 = __ldg(g_sorted_src + start + i + 3);
        float v0 = __ldg(x1f + (size_t)s0 * 8 + lane);
        float v1 = __ldg(x1f + (size_t)s1 * 8 + lane);
        float v2 = __ldg(x1f + (size_t)s2 * 8 + lane);
        float v3 = __ldg(x1f + (size_t)s3 * 8 + lane);
        acc += v0 + v1 + v2 + v3;
    }
    for (; i < cnt; i++) {
        int s = __ldg(g_sorted_src + start + i);
        acc += __ldg(x1f + (size_t)s * 8 + lane);
    }
    float innorm = rsqrtf(fmaxf((float)cnt, 1.f));
    float onorm  = rsqrtf(fmaxf((float)__ldg(&g_deg_out[n]), 1.f));
    float h = fmaxf(acc * innorm + sb[lane], 0.f);
    // o[k] = sum_j h_j * W2[j][k]
    float o0 = h * sW[lane * 4 + 0];
    float o1 = h * sW[lane * 4 + 1];
    float o2 = h * sW[lane * 4 + 2];
    float o3 = h * sW[lane * 4 + 3];
    unsigned full = 0xFFFFFFFFu;
#pragma unroll
    for (int off = 4; off > 0; off >>= 1) {             // xor 4,2,1 stays in 8-lane group
        o0 += __shfl_xor_sync(full, o0, off);
        o1 += __shfl_xor_sync(full, o1, off);
        o2 += __shfl_xor_sync(full, o2, off);
        o3 += __shfl_xor_sync(full, o3, off);
    }
    if (lane == 0)
        g_x2[n] = make_float4(o0 * onorm, o1 * onorm, o2 * onorm, o3 * onorm);
}

// gather layer 2: 4 threads per node (16B coalesced row loads), fused with
// graph-mean accumulation. Grid exact: 15625*256 = 4M.
__global__ void k_gather2(const int* __restrict__ graph_ids, const float* __restrict__ b2) {
    __shared__ float sb[4];
    if (threadIdx.x < 4) sb[threadIdx.x] = b2[threadIdx.x];
    __syncthreads();
    int t = threadIdx.x;
    int lane = t & 3;                                   // feature index
    int n = (blockIdx.x * blockDim.x + t) >> 2;         // node
    int start = __ldg(&g_offs[n]);
    int cnt   = __ldg(&g_deg_in[n]);
    const float* x2f = (const float*)g_x2;
    float acc = 0.f;
    int i = 0;
    for (; i + 3 < cnt; i += 4) {
        int s0 = __ldg(g_sorted_src + start + i);
        int s1 = __ldg(g_sorted_src + start + i + 1);
        int s2 = __ldg(g_sorted_src + start + i + 2);
        int s3 = __ldg(g_sorted_src + start + i + 3);
        float v0 = __ldg(x2f + (size_t)s0 * 4 + lane);
        float v1 = __ldg(x2f + (size_t)s1 * 4 + lane);
        float v2 = __ldg(x2f + (size_t)s2 * 4 + lane);
        float v3 = __ldg(x2f + (size_t)s3 * 4 + lane);
        acc += v0 + v1 + v2 + v3;
    }
    for (; i < cnt; i++) {
        int s = __ldg(g_sorted_src + start + i);
        acc += __ldg(x2f + (size_t)s * 4 + lane);
    }
    float innorm = rsqrtf(fmaxf((float)cnt, 1.f));
    float h = fmaxf(acc * innorm + sb[lane], 0.f);
    int gid = __ldg(graph_ids + n);

    unsigned full = 0xFFFFFFFFu;
    int g0 = __shfl_sync(full, gid, 0);
    bool uniform = __all_sync(full, gid == g0);
    if (uniform) {
        // sum h over the 8 node-groups in this warp (xor 4,8,16 keeps feature lane)
        h += __shfl_xor_sync(full, h, 4);
        h += __shfl_xor_sync(full, h, 8);
        h += __shfl_xor_sync(full, h, 16);
        int wl = t & 31;
        if (wl < 4)  atomicAdd(&g_gsum[g0 * 4 + wl], h);
        if (wl == 0) atomicAdd(&g_gcnt[g0], 8.f);
    } else {
        atomicAdd(&g_gsum[gid * 4 + lane], h);
        if (lane == 0) atomicAdd(&g_gcnt[gid], 1.f);
    }
}

__global__ void k_final(const float* __restrict__ Wo, const float* __restrict__ bo,
                        float* __restrict__ out) {
    int g = blockIdx.x * blockDim.x + threadIdx.x;
    if (g >= N_GRAPHS) return;
    float c = fmaxf(g_gcnt[g], 1.f);
    float z = __ldg(bo);
#pragma unroll
    for (int k = 0; k < 4; k++) z += (g_gsum[g * 4 + k] / c) * __ldg(Wo + k);
    out[g] = 1.f / (1.f + expf(-z));
}

// ---------------- launch ----------------
extern "C" void kernel_launch(void* const* d_in, const int* in_sizes, int n_in,
                              void* d_out, int out_size) {
    const float* feat      = (const float*)d_in[0];
    const int*   src       = (const int*)d_in[1];
    const int*   dst       = (const int*)d_in[2];
    const int*   graph_ids = (const int*)d_in[3];
    const float* W1        = (const float*)d_in[4];
    const float* b1        = (const float*)d_in[5];
    const float* W2        = (const float*)d_in[6];
    const float* b2        = (const float*)d_in[7];
    const float* Wo        = (const float*)d_in[8];
    const float* bo        = (const float*)d_in[9];
    float* out = (float*)d_out;

    const int T = 256;
    k_zero<<<(N_NODES / 4 + T - 1) / T, T>>>();
    k_degrees<<<((N_EDGES / 4) + T - 1) / T, T>>>(src, dst);
    k_scanA<<<SCAN_BLOCKS, 256>>>();
    k_scanB<<<1, 1024>>>();
    k_scanC<<<SCAN_BLOCKS, 256>>>();
    k_permute<<<((N_EDGES / 4) + T - 1) / T, T>>>(src, dst);
    k_proj1<<<(N_NODES + T - 1) / T, T>>>(feat, W1);
    k_gather1<<<(N_NODES * 8) / T, T>>>(W2, b1);
    k_gather2<<<(N_NODES * 4) / T, T>>>(graph_ids, b2);
    k_final<<<(N_GRAPHS + T - 1) / T, T>>>(Wo, bo, out);
}

// round 9
// speedup vs baseline: 1.2805x; 1.2805x over previous
#include <cuda_runtime.h>
#include <cuda_fp16.h>
#include <math.h>

#define N_NODES  1000000
#define N_EDGES  16000000
#define N_GRAPHS 1024

// ---------------- scratch (device globals: allocation-free) ----------------
__device__ __align__(16) float4   g_x1[2000000];        // x1: 1M x 8 fp32 (32 MB)
__device__ __align__(16) float4   g_x2[1000000];        // x2: 1M x 4 fp32 (16 MB)
__device__ __align__(16) unsigned g_agg1[N_NODES * 4];  // agg1: 1M x 8 fp16 (16 MB)
__device__ __align__(16) unsigned g_agg2[N_NODES * 2];  // agg2: 1M x 4 fp16 (8 MB)
__device__ __align__(16) int      g_deg_out[N_NODES];
__device__ __align__(16) int      g_deg_in[N_NODES];
__device__ float g_gsum[N_GRAPHS * 4];
__device__ float g_gcnt[N_GRAPHS];

__device__ __forceinline__ unsigned pack_h2(float x, float y) {
    __half2 h = __float22half2_rn(make_float2(x, y));
    return *reinterpret_cast<unsigned*>(&h);
}
__device__ __forceinline__ float2 unpack_h2(unsigned u) {
    __half2 h = *reinterpret_cast<__half2*>(&u);
    return __half22float2(h);
}

// 16B fp16 vector reduction: 8 halves in one atomic
__device__ __forceinline__ void red_add_v4h2(unsigned* p, unsigned a, unsigned b,
                                             unsigned c, unsigned d) {
    asm volatile("red.global.add.noftz.v4.f16x2 [%0], {%1,%2,%3,%4};"
                 :: "l"(p), "r"(a), "r"(b), "r"(c), "r"(d) : "memory");
}
// 8B fp16 vector reduction: 4 halves in one atomic
__device__ __forceinline__ void red_add_v2h2(unsigned* p, unsigned a, unsigned b) {
    asm volatile("red.global.add.noftz.v2.f16x2 [%0], {%1,%2};"
                 :: "l"(p), "r"(a), "r"(b) : "memory");
}

// ---------------- kernels ----------------

// zero agg1 (16MB), agg2 (8MB), degrees, graph accumulators
__global__ void k_zero() {
    int i = blockIdx.x * blockDim.x + threadIdx.x;
    int4 z4 = make_int4(0, 0, 0, 0);
    if (i < N_NODES)     ((int4*)g_agg1)[i] = z4;            // 1M x 16B
    if (i < N_NODES / 2) ((int4*)g_agg2)[i] = z4;            // 0.5M x 16B
    if (i < N_NODES / 4) { ((int4*)g_deg_out)[i] = z4;
                           ((int4*)g_deg_in)[i]  = z4; }
    if (i < N_GRAPHS) { ((float4*)g_gsum)[i] = make_float4(0.f,0.f,0.f,0.f);
                        g_gcnt[i] = 0.f; }
}

// degrees: 4 edges per thread
__global__ void k_degrees(const int* __restrict__ src, const int* __restrict__ dst) {
    int i = blockIdx.x * blockDim.x + threadIdx.x;
    if (i >= N_EDGES / 4) return;
    int4 s = ((const int4*)src)[i];
    int4 d = ((const int4*)dst)[i];
    atomicAdd(&g_deg_out[s.x], 1); atomicAdd(&g_deg_out[s.y], 1);
    atomicAdd(&g_deg_out[s.z], 1); atomicAdd(&g_deg_out[s.w], 1);
    atomicAdd(&g_deg_in[d.x], 1);  atomicAdd(&g_deg_in[d.y], 1);
    atomicAdd(&g_deg_in[d.z], 1);  atomicAdd(&g_deg_in[d.w], 1);
}

// x1 = (features * out_norm) @ W1  (fp32, 32B rows)
__global__ void k_proj1(const float* __restrict__ feat, const float* __restrict__ W1) {
    __shared__ float sW[80];
    if (threadIdx.x < 80) sW[threadIdx.x] = W1[threadIdx.x];
    __syncthreads();
    int n = blockIdx.x * blockDim.x + threadIdx.x;
    if (n >= N_NODES) return;
    float onorm = rsqrtf(fmaxf((float)g_deg_out[n], 1.f));
    const float2* fp = (const float2*)(feat + (size_t)n * 10);
    float f[10];
#pragma unroll
    for (int i = 0; i < 5; i++) { float2 v = fp[i]; f[2*i] = v.x * onorm; f[2*i+1] = v.y * onorm; }
    float o[8];
#pragma unroll
    for (int j = 0; j < 8; j++) o[j] = 0.f;
#pragma unroll
    for (int i = 0; i < 10; i++)
#pragma unroll
        for (int j = 0; j < 8; j++) o[j] += f[i] * sW[i * 8 + j];
    g_x1[n * 2]     = make_float4(o[0], o[1], o[2], o[3]);
    g_x1[n * 2 + 1] = make_float4(o[4], o[5], o[6], o[7]);
}

// agg1[dst] += fp16(x1[src])  -- ONE 16B vector atomic per edge
__global__ void k_scatter1(const int* __restrict__ src, const int* __restrict__ dst) {
    int e = blockIdx.x * blockDim.x + threadIdx.x;
    if (e >= N_EDGES) return;
    int s = __ldg(src + e);
    int d = __ldg(dst + e);
    float4 v0 = __ldg(&g_x1[(size_t)s * 2]);
    float4 v1 = __ldg(&g_x1[(size_t)s * 2 + 1]);
    unsigned a = pack_h2(v0.x, v0.y);
    unsigned b = pack_h2(v0.z, v0.w);
    unsigned c = pack_h2(v1.x, v1.y);
    unsigned dd = pack_h2(v1.z, v1.w);
    red_add_v4h2(&g_agg1[(size_t)d * 4], a, b, c, dd);
}

// h1 = relu(fp32(agg1) * in_norm + b1); x2 = (h1 * out_norm) @ W2 (fp32)
__global__ void k_h1_proj2(const float* __restrict__ W2, const float* __restrict__ b1) {
    __shared__ float sW[32], sb[8];
    if (threadIdx.x < 32) sW[threadIdx.x] = W2[threadIdx.x];
    if (threadIdx.x < 8)  sb[threadIdx.x] = b1[threadIdx.x];
    __syncthreads();
    int n = blockIdx.x * blockDim.x + threadIdx.x;
    if (n >= N_NODES) return;
    float innorm = rsqrtf(fmaxf((float)g_deg_in[n], 1.f));
    float onorm  = rsqrtf(fmaxf((float)g_deg_out[n], 1.f));
    uint4 raw = ((const uint4*)g_agg1)[n];
    float2 p0 = unpack_h2(raw.x), p1 = unpack_h2(raw.y);
    float2 p2 = unpack_h2(raw.z), p3 = unpack_h2(raw.w);
    float h[8] = { p0.x, p0.y, p1.x, p1.y, p2.x, p2.y, p3.x, p3.y };
#pragma unroll
    for (int j = 0; j < 8; j++) h[j] = fmaxf(h[j] * innorm + sb[j], 0.f);
    float o[4] = {0.f, 0.f, 0.f, 0.f};
#pragma unroll
    for (int j = 0; j < 8; j++)
#pragma unroll
        for (int k = 0; k < 4; k++) o[k] += h[j] * sW[j * 4 + k];
    g_x2[n] = make_float4(o[0] * onorm, o[1] * onorm, o[2] * onorm, o[3] * onorm);
}

// agg2[dst] += fp16(x2[src])  -- ONE 8B vector atomic per edge
__global__ void k_scatter2(const int* __restrict__ src, const int* __restrict__ dst) {
    int e = blockIdx.x * blockDim.x + threadIdx.x;
    if (e >= N_EDGES) return;
    int s = __ldg(src + e);
    int d = __ldg(dst + e);
    float4 v = __ldg(&g_x2[s]);
    unsigned a = pack_h2(v.x, v.y);
    unsigned b = pack_h2(v.z, v.w);
    red_add_v2h2(&g_agg2[(size_t)d * 2], a, b);
}

// h2 = relu(fp32(agg2) * in_norm + b2); per-graph mean accumulation
// (graph_ids sorted -> warps almost always gid-uniform)
__global__ void k_graph_reduce(const int* __restrict__ graph_ids, const float* __restrict__ b2) {
    int n0 = blockIdx.x * blockDim.x + threadIdx.x;
    bool valid = (n0 < N_NODES);
    int n = valid ? n0 : (N_NODES - 1);
    uint2 raw = ((const uint2*)g_agg2)[n];
    float2 p0 = unpack_h2(raw.x), p1 = unpack_h2(raw.y);
    float innorm = rsqrtf(fmaxf((float)g_deg_in[n], 1.f));
    float h[4];
    h[0] = valid ? fmaxf(p0.x * innorm + __ldg(b2 + 0), 0.f) : 0.f;
    h[1] = valid ? fmaxf(p0.y * innorm + __ldg(b2 + 1), 0.f) : 0.f;
    h[2] = valid ? fmaxf(p1.x * innorm + __ldg(b2 + 2), 0.f) : 0.f;
    h[3] = valid ? fmaxf(p1.y * innorm + __ldg(b2 + 3), 0.f) : 0.f;
    float cnt = valid ? 1.f : 0.f;
    int gid = __ldg(graph_ids + n);

    unsigned full = 0xFFFFFFFFu;
    int g0 = __shfl_sync(full, gid, 0);
    bool uniform = __all_sync(full, gid == g0);
    int lane = threadIdx.x & 31;
    if (uniform) {
#pragma unroll
        for (int off = 16; off > 0; off >>= 1) {
#pragma unroll
            for (int k = 0; k < 4; k++) h[k] += __shfl_down_sync(full, h[k], off);
            cnt += __shfl_down_sync(full, cnt, off);
        }
        if (lane == 0) {
#pragma unroll
            for (int k = 0; k < 4; k++) atomicAdd(&g_gsum[g0 * 4 + k], h[k]);
            atomicAdd(&g_gcnt[g0], cnt);
        }
    } else if (valid) {
#pragma unroll
        for (int k = 0; k < 4; k++) atomicAdd(&g_gsum[gid * 4 + k], h[k]);
        atomicAdd(&g_gcnt[gid], 1.f);
    }
}

// out[g] = sigmoid(mean @ Wo + bo)
__global__ void k_final(const float* __restrict__ Wo, const float* __restrict__ bo,
                        float* __restrict__ out) {
    int g = blockIdx.x * blockDim.x + threadIdx.x;
    if (g >= N_GRAPHS) return;
    float c = fmaxf(g_gcnt[g], 1.f);
    float z = __ldg(bo);
#pragma unroll
    for (int k = 0; k < 4; k++) z += (g_gsum[g * 4 + k] / c) * __ldg(Wo + k);
    out[g] = 1.f / (1.f + expf(-z));
}

// ---------------- launch ----------------
extern "C" void kernel_launch(void* const* d_in, const int* in_sizes, int n_in,
                              void* d_out, int out_size) {
    const float* feat      = (const float*)d_in[0];
    const int*   src       = (const int*)d_in[1];
    const int*   dst       = (const int*)d_in[2];
    const int*   graph_ids = (const int*)d_in[3];
    const float* W1        = (const float*)d_in[4];
    const float* b1        = (const float*)d_in[5];
    const float* W2        = (const float*)d_in[6];
    const float* b2        = (const float*)d_in[7];
    const float* Wo        = (const float*)d_in[8];
    const float* bo        = (const float*)d_in[9];
    float* out = (float*)d_out;

    const int T = 256;
    // scatter1 kept as the 4th launch so ncu profiles it (matches R6 capture slot)
    k_zero<<<(N_NODES + T - 1) / T, T>>>();
    k_degrees<<<((N_EDGES / 4) + T - 1) / T, T>>>(src, dst);
    k_proj1<<<(N_NODES + T - 1) / T, T>>>(feat, W1);
    k_scatter1<<<(N_EDGES + T - 1) / T, T>>>(src, dst);
    k_h1_proj2<<<(N_NODES + T - 1) / T, T>>>(W2, b1);
    k_scatter2<<<(N_EDGES + T - 1) / T, T>>>(src, dst);
    k_graph_reduce<<<(N_NODES + T - 1) / T, T>>>(graph_ids, b2);
    k_final<<<(N_GRAPHS + T - 1) / T, T>>>(Wo, bo, out);
}

// round 10
// speedup vs baseline: 1.3811x; 1.0786x over previous
#include <cuda_runtime.h>
#include <cuda_fp16.h>
#include <math.h>

#define N_NODES  1000000
#define N_EDGES  16000000
#define N_GRAPHS 1024

// ---------------- scratch (device globals: allocation-free) ----------------
__device__ __align__(16) uint4    g_x1h[N_NODES];       // x1: 1M x 8 fp16 (16 MB)
__device__ __align__(16) uint2    g_x2h[N_NODES];       // x2: 1M x 4 fp16 (8 MB)
__device__ __align__(16) unsigned g_agg1[N_NODES * 4];  // agg1: 1M x 8 fp16 (16 MB)
__device__ __align__(16) unsigned g_agg2[N_NODES * 2];  // agg2: 1M x 4 fp16 (8 MB)
__device__ __align__(16) int      g_deg_out[N_NODES];
__device__ __align__(16) int      g_deg_in[N_NODES];
__device__ float g_gsum[N_GRAPHS * 4];
__device__ float g_gcnt[N_GRAPHS];

__device__ __forceinline__ unsigned pack_h2(float x, float y) {
    __half2 h = __float22half2_rn(make_float2(x, y));
    return *reinterpret_cast<unsigned*>(&h);
}
__device__ __forceinline__ float2 unpack_h2(unsigned u) {
    __half2 h = *reinterpret_cast<__half2*>(&u);
    return __half22float2(h);
}

// 16B fp16 vector reduction: 8 halves in one atomic
__device__ __forceinline__ void red_add_v4h2(unsigned* p, uint4 v) {
    asm volatile("red.global.add.noftz.v4.f16x2 [%0], {%1,%2,%3,%4};"
                 :: "l"(p), "r"(v.x), "r"(v.y), "r"(v.z), "r"(v.w) : "memory");
}
// 8B fp16 vector reduction: 4 halves in one atomic
__device__ __forceinline__ void red_add_v2h2(unsigned* p, uint2 v) {
    asm volatile("red.global.add.noftz.v2.f16x2 [%0], {%1,%2};"
                 :: "l"(p), "r"(v.x), "r"(v.y) : "memory");
}

// ---------------- kernels ----------------

// zero agg1 (16MB), agg2 (8MB), degrees, graph accumulators
__global__ void k_zero() {
    int i = blockIdx.x * blockDim.x + threadIdx.x;
    int4 z4 = make_int4(0, 0, 0, 0);
    if (i < N_NODES)     ((int4*)g_agg1)[i] = z4;
    if (i < N_NODES / 2) ((int4*)g_agg2)[i] = z4;
    if (i < N_NODES / 4) { ((int4*)g_deg_out)[i] = z4;
                           ((int4*)g_deg_in)[i]  = z4; }
    if (i < N_GRAPHS) { ((float4*)g_gsum)[i] = make_float4(0.f,0.f,0.f,0.f);
                        g_gcnt[i] = 0.f; }
}

// degrees: 4 edges per thread
__global__ void k_degrees(const int* __restrict__ src, const int* __restrict__ dst) {
    int i = blockIdx.x * blockDim.x + threadIdx.x;
    if (i >= N_EDGES / 4) return;
    int4 s = ((const int4*)src)[i];
    int4 d = ((const int4*)dst)[i];
    atomicAdd(&g_deg_out[s.x], 1); atomicAdd(&g_deg_out[s.y], 1);
    atomicAdd(&g_deg_out[s.z], 1); atomicAdd(&g_deg_out[s.w], 1);
    atomicAdd(&g_deg_in[d.x], 1);  atomicAdd(&g_deg_in[d.y], 1);
    atomicAdd(&g_deg_in[d.z], 1);  atomicAdd(&g_deg_in[d.w], 1);
}

// x1 = (features * out_norm) @ W1, stored fp16-packed (16B rows)
__global__ void k_proj1(const float* __restrict__ feat, const float* __restrict__ W1) {
    __shared__ float sW[80];
    if (threadIdx.x < 80) sW[threadIdx.x] = W1[threadIdx.x];
    __syncthreads();
    int n = blockIdx.x * blockDim.x + threadIdx.x;
    if (n >= N_NODES) return;
    float onorm = rsqrtf(fmaxf((float)g_deg_out[n], 1.f));
    const float2* fp = (const float2*)(feat + (size_t)n * 10);
    float f[10];
#pragma unroll
    for (int i = 0; i < 5; i++) { float2 v = fp[i]; f[2*i] = v.x * onorm; f[2*i+1] = v.y * onorm; }
    float o[8];
#pragma unroll
    for (int j = 0; j < 8; j++) o[j] = 0.f;
#pragma unroll
    for (int i = 0; i < 10; i++)
#pragma unroll
        for (int j = 0; j < 8; j++) o[j] += f[i] * sW[i * 8 + j];
    g_x1h[n] = make_uint4(pack_h2(o[0], o[1]), pack_h2(o[2], o[3]),
                          pack_h2(o[4], o[5]), pack_h2(o[6], o[7]));
}

// agg1[dst] += x1h[src]  -- 2 edges/thread, one 16B gather + one 16B RED each
__global__ void k_scatter1(const int* __restrict__ src, const int* __restrict__ dst) {
    int i = blockIdx.x * blockDim.x + threadIdx.x;   // i < N_EDGES/2
    int2 s = __ldg((const int2*)src + i);
    int2 d = __ldg((const int2*)dst + i);
    uint4 v0 = __ldg(&g_x1h[s.x]);
    uint4 v1 = __ldg(&g_x1h[s.y]);
    red_add_v4h2(&g_agg1[(size_t)d.x * 4], v0);
    red_add_v4h2(&g_agg1[(size_t)d.y * 4], v1);
}

// h1 = relu(fp32(agg1) * in_norm + b1); x2 = (h1 * out_norm) @ W2, fp16-packed
__global__ void k_h1_proj2(const float* __restrict__ W2, const float* __restrict__ b1) {
    __shared__ float sW[32], sb[8];
    if (threadIdx.x < 32) sW[threadIdx.x] = W2[threadIdx.x];
    if (threadIdx.x < 8)  sb[threadIdx.x] = b1[threadIdx.x];
    __syncthreads();
    int n = blockIdx.x * blockDim.x + threadIdx.x;
    if (n >= N_NODES) return;
    float innorm = rsqrtf(fmaxf((float)g_deg_in[n], 1.f));
    float onorm  = rsqrtf(fmaxf((float)g_deg_out[n], 1.f));
    uint4 raw = ((const uint4*)g_agg1)[n];
    float2 p0 = unpack_h2(raw.x), p1 = unpack_h2(raw.y);
    float2 p2 = unpack_h2(raw.z), p3 = unpack_h2(raw.w);
    float h[8] = { p0.x, p0.y, p1.x, p1.y, p2.x, p2.y, p3.x, p3.y };
#pragma unroll
    for (int j = 0; j < 8; j++) h[j] = fmaxf(h[j] * innorm + sb[j], 0.f);
    float o[4] = {0.f, 0.f, 0.f, 0.f};
#pragma unroll
    for (int j = 0; j < 8; j++)
#pragma unroll
        for (int k = 0; k < 4; k++) o[k] += h[j] * sW[j * 4 + k];
    g_x2h[n] = make_uint2(pack_h2(o[0] * onorm, o[1] * onorm),
                          pack_h2(o[2] * onorm, o[3] * onorm));
}

// agg2[dst] += x2h[src]  -- 2 edges/thread, one 8B gather + one 8B RED each
__global__ void k_scatter2(const int* __restrict__ src, const int* __restrict__ dst) {
    int i = blockIdx.x * blockDim.x + threadIdx.x;   // i < N_EDGES/2
    int2 s = __ldg((const int2*)src + i);
    int2 d = __ldg((const int2*)dst + i);
    uint2 v0 = __ldg(&g_x2h[s.x]);
    uint2 v1 = __ldg(&g_x2h[s.y]);
    red_add_v2h2(&g_agg2[(size_t)d.x * 2], v0);
    red_add_v2h2(&g_agg2[(size_t)d.y * 2], v1);
}

// h2 = relu(fp32(agg2) * in_norm + b2); per-graph mean accumulation
__global__ void k_graph_reduce(const int* __restrict__ graph_ids, const float* __restrict__ b2) {
    int n0 = blockIdx.x * blockDim.x + threadIdx.x;
    bool valid = (n0 < N_NODES);
    int n = valid ? n0 : (N_NODES - 1);
    uint2 raw = ((const uint2*)g_agg2)[n];
    float2 p0 = unpack_h2(raw.x), p1 = unpack_h2(raw.y);
    float innorm = rsqrtf(fmaxf((float)g_deg_in[n], 1.f));
    float h[4];
    h[0] = valid ? fmaxf(p0.x * innorm + __ldg(b2 + 0), 0.f) : 0.f;
    h[1] = valid ? fmaxf(p0.y * innorm + __ldg(b2 + 1), 0.f) : 0.f;
    h[2] = valid ? fmaxf(p1.x * innorm + __ldg(b2 + 2), 0.f) : 0.f;
    h[3] = valid ? fmaxf(p1.y * innorm + __ldg(b2 + 3), 0.f) : 0.f;
    float cnt = valid ? 1.f : 0.f;
    int gid = __ldg(graph_ids + n);

    unsigned full = 0xFFFFFFFFu;
    int g0 = __shfl_sync(full, gid, 0);
    bool uniform = __all_sync(full, gid == g0);
    int lane = threadIdx.x & 31;
    if (uniform) {
#pragma unroll
        for (int off = 16; off > 0; off >>= 1) {
#pragma unroll
            for (int k = 0; k < 4; k++) h[k] += __shfl_down_sync(full, h[k], off);
            cnt += __shfl_down_sync(full, cnt, off);
        }
        if (lane == 0) {
#pragma unroll
            for (int k = 0; k < 4; k++) atomicAdd(&g_gsum[g0 * 4 + k], h[k]);
            atomicAdd(&g_gcnt[g0], cnt);
        }
    } else if (valid) {
#pragma unroll
        for (int k = 0; k < 4; k++) atomicAdd(&g_gsum[gid * 4 + k], h[k]);
        atomicAdd(&g_gcnt[gid], 1.f);
    }
}

// out[g] = sigmoid(mean @ Wo + bo)
__global__ void k_final(const float* __restrict__ Wo, const float* __restrict__ bo,
                        float* __restrict__ out) {
    int g = blockIdx.x * blockDim.x + threadIdx.x;
    if (g >= N_GRAPHS) return;
    float c = fmaxf(g_gcnt[g], 1.f);
    float z = __ldg(bo);
#pragma unroll
    for (int k = 0; k < 4; k++) z += (g_gsum[g * 4 + k] / c) * __ldg(Wo + k);
    out[g] = 1.f / (1.f + expf(-z));
}

// ---------------- launch ----------------
extern "C" void kernel_launch(void* const* d_in, const int* in_sizes, int n_in,
                              void* d_out, int out_size) {
    const float* feat      = (const float*)d_in[0];
    const int*   src       = (const int*)d_in[1];
    const int*   dst       = (const int*)d_in[2];
    const int*   graph_ids = (const int*)d_in[3];
    const float* W1        = (const float*)d_in[4];
    const float* b1        = (const float*)d_in[5];
    const float* W2        = (const float*)d_in[6];
    const float* b2        = (const float*)d_in[7];
    const float* Wo        = (const float*)d_in[8];
    const float* bo        = (const float*)d_in[9];
    float* out = (float*)d_out;

    const int T = 256;
    // scatter1 kept as the 4th launch so ncu profiles it (same capture slot)
    k_zero<<<(N_NODES + T - 1) / T, T>>>();
    k_degrees<<<((N_EDGES / 4) + T - 1) / T, T>>>(src, dst);
    k_proj1<<<(N_NODES + T - 1) / T, T>>>(feat, W1);
    k_scatter1<<<(N_EDGES / 2) / T, T>>>(src, dst);
    k_h1_proj2<<<(N_NODES + T - 1) / T, T>>>(W2, b1);
    k_scatter2<<<(N_EDGES / 2) / T, T>>>(src, dst);
    k_graph_reduce<<<(N_NODES + T - 1) / T, T>>>(graph_ids, b2);
    k_final<<<(N_GRAPHS + T - 1) / T, T>>>(Wo, bo, out);
}

// round 11
// speedup vs baseline: 1.3871x; 1.0044x over previous
#include <cuda_runtime.h>
#include <cuda_fp16.h>
#include <math.h>

#define N_NODES  1000000
#define N_EDGES  16000000
#define N_GRAPHS 1024

// ---------------- scratch (device globals: allocation-free) ----------------
__device__ __align__(16) uint4    g_x1h[N_NODES];       // x1: 1M x 8 fp16 (16 MB)
__device__ __align__(16) uint2    g_x2h[N_NODES];       // x2: 1M x 4 fp16 (8 MB)
__device__ __align__(16) unsigned g_agg1[N_NODES * 4];  // agg1: 1M x 8 fp16 (16 MB)
__device__ __align__(16) unsigned g_agg2[N_NODES * 2];  // agg2: 1M x 4 fp16 (8 MB)
__device__ __align__(16) int      g_deg_out[N_NODES];
__device__ __align__(16) int      g_deg_in[N_NODES];
__device__ float g_gsum[N_GRAPHS * 4];
__device__ float g_gcnt[N_GRAPHS];

__device__ __forceinline__ unsigned pack_h2(float x, float y) {
    __half2 h = __float22half2_rn(make_float2(x, y));
    return *reinterpret_cast<unsigned*>(&h);
}
__device__ __forceinline__ float2 unpack_h2(unsigned u) {
    __half2 h = *reinterpret_cast<__half2*>(&u);
    return __half22float2(h);
}

__device__ __forceinline__ void red_add_v4h2(unsigned* p, uint4 v) {
    asm volatile("red.global.add.noftz.v4.f16x2 [%0], {%1,%2,%3,%4};"
                 :: "l"(p), "r"(v.x), "r"(v.y), "r"(v.z), "r"(v.w) : "memory");
}
__device__ __forceinline__ void red_add_v2h2(unsigned* p, uint2 v) {
    asm volatile("red.global.add.noftz.v2.f16x2 [%0], {%1,%2};"
                 :: "l"(p), "r"(v.x), "r"(v.y) : "memory");
}

// PDL helpers: trigger early so the dependent kernel's CTAs roll out during
// our tail; dependent syncs before touching our writes.
__device__ __forceinline__ void pdl_begin() {
    cudaTriggerProgrammaticLaunchCompletion();
    cudaGridDependencySynchronize();
}

// ---------------- kernels ----------------

// zero agg1 (16MB) + degree arrays (agg2/gsum/gcnt are zeroed in k_h1_proj2)
__global__ void k_zero() {
    pdl_begin();
    int i = blockIdx.x * blockDim.x + threadIdx.x;
    int4 z4 = make_int4(0, 0, 0, 0);
    if (i < N_NODES)     ((int4*)g_agg1)[i] = z4;
    if (i < N_NODES / 4) { ((int4*)g_deg_out)[i] = z4;
                           ((int4*)g_deg_in)[i]  = z4; }
}

// degrees: 8 edges per thread
__global__ void k_degrees(const int* __restrict__ src, const int* __restrict__ dst) {
    pdl_begin();
    int i = blockIdx.x * blockDim.x + threadIdx.x;
    if (i >= N_EDGES / 8) return;
    int4 s0 = ((const int4*)src)[2 * i],   s1 = ((const int4*)src)[2 * i + 1];
    int4 d0 = ((const int4*)dst)[2 * i],   d1 = ((const int4*)dst)[2 * i + 1];
    atomicAdd(&g_deg_out[s0.x], 1); atomicAdd(&g_deg_out[s0.y], 1);
    atomicAdd(&g_deg_out[s0.z], 1); atomicAdd(&g_deg_out[s0.w], 1);
    atomicAdd(&g_deg_out[s1.x], 1); atomicAdd(&g_deg_out[s1.y], 1);
    atomicAdd(&g_deg_out[s1.z], 1); atomicAdd(&g_deg_out[s1.w], 1);
    atomicAdd(&g_deg_in[d0.x], 1);  atomicAdd(&g_deg_in[d0.y], 1);
    atomicAdd(&g_deg_in[d0.z], 1);  atomicAdd(&g_deg_in[d0.w], 1);
    atomicAdd(&g_deg_in[d1.x], 1);  atomicAdd(&g_deg_in[d1.y], 1);
    atomicAdd(&g_deg_in[d1.z], 1);  atomicAdd(&g_deg_in[d1.w], 1);
}

// x1 = (features * out_norm) @ W1, stored fp16-packed (16B rows)
__global__ void k_proj1(const float* __restrict__ feat, const float* __restrict__ W1) {
    pdl_begin();
    __shared__ float sW[80];
    if (threadIdx.x < 80) sW[threadIdx.x] = W1[threadIdx.x];
    __syncthreads();
    int n = blockIdx.x * blockDim.x + threadIdx.x;
    if (n >= N_NODES) return;
    float onorm = rsqrtf(fmaxf((float)g_deg_out[n], 1.f));
    const float2* fp = (const float2*)(feat + (size_t)n * 10);
    float f[10];
#pragma unroll
    for (int i = 0; i < 5; i++) { float2 v = fp[i]; f[2*i] = v.x * onorm; f[2*i+1] = v.y * onorm; }
    float o[8];
#pragma unroll
    for (int j = 0; j < 8; j++) o[j] = 0.f;
#pragma unroll
    for (int i = 0; i < 10; i++)
#pragma unroll
        for (int j = 0; j < 8; j++) o[j] += f[i] * sW[i * 8 + j];
    g_x1h[n] = make_uint4(pack_h2(o[0], o[1]), pack_h2(o[2], o[3]),
                          pack_h2(o[4], o[5]), pack_h2(o[6], o[7]));
}

// agg1[dst] += x1h[src]  -- 4 edges/thread: int4 idx, 4 gathers, 4 REDs
__global__ void k_scatter1(const int* __restrict__ src, const int* __restrict__ dst) {
    pdl_begin();
    int i = blockIdx.x * blockDim.x + threadIdx.x;   // i < N_EDGES/4
    int4 s = ((const int4*)src)[i];
    int4 d = ((const int4*)dst)[i];
    uint4 v0 = __ldg(&g_x1h[s.x]);
    uint4 v1 = __ldg(&g_x1h[s.y]);
    uint4 v2 = __ldg(&g_x1h[s.z]);
    uint4 v3 = __ldg(&g_x1h[s.w]);
    red_add_v4h2(&g_agg1[(size_t)d.x * 4], v0);
    red_add_v4h2(&g_agg1[(size_t)d.y * 4], v1);
    red_add_v4h2(&g_agg1[(size_t)d.z * 4], v2);
    red_add_v4h2(&g_agg1[(size_t)d.w * 4], v3);
}

// h1 = relu(fp32(agg1)*in_norm + b1); x2 = (h1*out_norm) @ W2 fp16-packed.
// Also zeroes agg2 and the graph accumulators (consumed two kernels later).
__global__ void k_h1_proj2(const float* __restrict__ W2, const float* __restrict__ b1) {
    pdl_begin();
    __shared__ float sW[32], sb[8];
    if (threadIdx.x < 32) sW[threadIdx.x] = W2[threadIdx.x];
    if (threadIdx.x < 8)  sb[threadIdx.x] = b1[threadIdx.x];
    __syncthreads();
    int n = blockIdx.x * blockDim.x + threadIdx.x;
    if (n >= N_NODES) return;
    ((uint2*)g_agg2)[n] = make_uint2(0u, 0u);
    if (n < N_GRAPHS) { ((float4*)g_gsum)[n] = make_float4(0.f,0.f,0.f,0.f);
                        g_gcnt[n] = 0.f; }
    float innorm = rsqrtf(fmaxf((float)g_deg_in[n], 1.f));
    float onorm  = rsqrtf(fmaxf((float)g_deg_out[n], 1.f));
    uint4 raw = ((const uint4*)g_agg1)[n];
    float2 p0 = unpack_h2(raw.x), p1 = unpack_h2(raw.y);
    float2 p2 = unpack_h2(raw.z), p3 = unpack_h2(raw.w);
    float h[8] = { p0.x, p0.y, p1.x, p1.y, p2.x, p2.y, p3.x, p3.y };
#pragma unroll
    for (int j = 0; j < 8; j++) h[j] = fmaxf(h[j] * innorm + sb[j], 0.f);
    float o[4] = {0.f, 0.f, 0.f, 0.f};
#pragma unroll
    for (int j = 0; j < 8; j++)
#pragma unroll
        for (int k = 0; k < 4; k++) o[k] += h[j] * sW[j * 4 + k];
    g_x2h[n] = make_uint2(pack_h2(o[0] * onorm, o[1] * onorm),
                          pack_h2(o[2] * onorm, o[3] * onorm));
}

// agg2[dst] += x2h[src]  -- 4 edges/thread
__global__ void k_scatter2(const int* __restrict__ src, const int* __restrict__ dst) {
    pdl_begin();
    int i = blockIdx.x * blockDim.x + threadIdx.x;   // i < N_EDGES/4
    int4 s = ((const int4*)src)[i];
    int4 d = ((const int4*)dst)[i];
    uint2 v0 = __ldg(&g_x2h[s.x]);
    uint2 v1 = __ldg(&g_x2h[s.y]);
    uint2 v2 = __ldg(&g_x2h[s.z]);
    uint2 v3 = __ldg(&g_x2h[s.w]);
    red_add_v2h2(&g_agg2[(size_t)d.x * 2], v0);
    red_add_v2h2(&g_agg2[(size_t)d.y * 2], v1);
    red_add_v2h2(&g_agg2[(size_t)d.z * 2], v2);
    red_add_v2h2(&g_agg2[(size_t)d.w * 2], v3);
}

// h2 = relu(fp32(agg2) * in_norm + b2); per-graph mean accumulation
__global__ void k_graph_reduce(const int* __restrict__ graph_ids, const float* __restrict__ b2) {
    pdl_begin();
    int n0 = blockIdx.x * blockDim.x + threadIdx.x;
    bool valid = (n0 < N_NODES);
    int n = valid ? n0 : (N_NODES - 1);
    uint2 raw = ((const uint2*)g_agg2)[n];
    float2 p0 = unpack_h2(raw.x), p1 = unpack_h2(raw.y);
    float innorm = rsqrtf(fmaxf((float)g_deg_in[n], 1.f));
    float h[4];
    h[0] = valid ? fmaxf(p0.x * innorm + __ldg(b2 + 0), 0.f) : 0.f;
    h[1] = valid ? fmaxf(p0.y * innorm + __ldg(b2 + 1), 0.f) : 0.f;
    h[2] = valid ? fmaxf(p1.x * innorm + __ldg(b2 + 2), 0.f) : 0.f;
    h[3] = valid ? fmaxf(p1.y * innorm + __ldg(b2 + 3), 0.f) : 0.f;
    float cnt = valid ? 1.f : 0.f;
    int gid = __ldg(graph_ids + n);

    unsigned full = 0xFFFFFFFFu;
    int g0 = __shfl_sync(full, gid, 0);
    bool uniform = __all_sync(full, gid == g0);
    int lane = threadIdx.x & 31;
    if (uniform) {
#pragma unroll
        for (int off = 16; off > 0; off >>= 1) {
#pragma unroll
            for (int k = 0; k < 4; k++) h[k] += __shfl_down_sync(full, h[k], off);
            cnt += __shfl_down_sync(full, cnt, off);
        }
        if (lane == 0) {
#pragma unroll
            for (int k = 0; k < 4; k++) atomicAdd(&g_gsum[g0 * 4 + k], h[k]);
            atomicAdd(&g_gcnt[g0], cnt);
        }
    } else if (valid) {
#pragma unroll
        for (int k = 0; k < 4; k++) atomicAdd(&g_gsum[gid * 4 + k], h[k]);
        atomicAdd(&g_gcnt[gid], 1.f);
    }
}

// out[g] = sigmoid(mean @ Wo + bo)
__global__ void k_final(const float* __restrict__ Wo, const float* __restrict__ bo,
                        float* __restrict__ out) {
    pdl_begin();
    int g = blockIdx.x * blockDim.x + threadIdx.x;
    if (g >= N_GRAPHS) return;
    float c = fmaxf(g_gcnt[g], 1.f);
    float z = __ldg(bo);
#pragma unroll
    for (int k = 0; k < 4; k++) z += (g_gsum[g * 4 + k] / c) * __ldg(Wo + k);
    out[g] = 1.f / (1.f + expf(-z));
}

// ---------------- launch (PDL on every boundary) ----------------
template <typename... Args>
static void launch_pdl(void (*kern)(Args...), int grid, int block, Args... args) {
    cudaLaunchConfig_t cfg = {};
    cfg.gridDim = dim3(grid, 1, 1);
    cfg.blockDim = dim3(block, 1, 1);
    cfg.stream = 0;
    cudaLaunchAttribute attr[1];
    attr[0].id = cudaLaunchAttributeProgrammaticStreamSerialization;
    attr[0].val.programmaticStreamSerializationAllowed = 1;
    cfg.attrs = attr;
    cfg.numAttrs = 1;
    cudaLaunchKernelEx(&cfg, kern, args...);
}

extern "C" void kernel_launch(void* const* d_in, const int* in_sizes, int n_in,
                              void* d_out, int out_size) {
    const float* feat      = (const float*)d_in[0];
    const int*   src       = (const int*)d_in[1];
    const int*   dst       = (const int*)d_in[2];
    const int*   graph_ids = (const int*)d_in[3];
    const float* W1        = (const float*)d_in[4];
    const float* b1        = (const float*)d_in[5];
    const float* W2        = (const float*)d_in[6];
    const float* b2        = (const float*)d_in[7];
    const float* Wo        = (const float*)d_in[8];
    const float* bo        = (const float*)d_in[9];
    float* out = (float*)d_out;

    const int T = 256;
    launch_pdl(k_zero,    (N_NODES + T - 1) / T, T);
    launch_pdl(k_degrees, (N_EDGES / 8 + T - 1) / T, T, src, dst);
    launch_pdl(k_proj1,   (N_NODES + T - 1) / T, T, feat, W1);
    launch_pdl(k_scatter1, (N_EDGES / 4) / T, T, src, dst);
    launch_pdl(k_h1_proj2, (N_NODES + T - 1) / T, T, W2, b1);
    launch_pdl(k_scatter2, (N_EDGES / 4) / T, T, src, dst);
    launch_pdl(k_graph_reduce, (N_NODES + T - 1) / T, T, graph_ids, b2);
    launch_pdl(k_final,   (N_GRAPHS + T - 1) / T, T, Wo, bo, out);
}

// round 12
// speedup vs baseline: 1.4060x; 1.0136x over previous
#include <cuda_runtime.h>
#include <cuda_fp16.h>
#include <math.h>

#define N_NODES  1000000
#define N_EDGES  16000000
#define N_GRAPHS 1024

// ---------------- scratch (device globals: allocation-free) ----------------
__device__ __align__(16) uint4    g_x1h[N_NODES];       // x1: 1M x 8 fp16 (16 MB)
__device__ __align__(16) uint2    g_x2h[N_NODES];       // x2: 1M x 4 fp16 (8 MB)
__device__ __align__(16) unsigned g_agg1[N_NODES * 4];  // agg1: 1M x 8 fp16 (16 MB)
__device__ __align__(16) unsigned g_agg2[N_NODES * 2];  // agg2: 1M x 4 fp16 (8 MB)
__device__ __align__(16) int      g_deg_out[N_NODES];
__device__ __align__(16) int      g_deg_in[N_NODES];
__device__ float g_gsum[N_GRAPHS * 4];
__device__ float g_gcnt[N_GRAPHS];

__device__ __forceinline__ unsigned pack_h2(float x, float y) {
    __half2 h = __float22half2_rn(make_float2(x, y));
    return *reinterpret_cast<unsigned*>(&h);
}
__device__ __forceinline__ float2 unpack_h2(unsigned u) {
    __half2 h = *reinterpret_cast<__half2*>(&u);
    return __half22float2(h);
}

__device__ __forceinline__ void red_add_v4h2(unsigned* p, uint4 v) {
    asm volatile("red.global.add.noftz.v4.f16x2 [%0], {%1,%2,%3,%4};"
                 :: "l"(p), "r"(v.x), "r"(v.y), "r"(v.z), "r"(v.w) : "memory");
}
__device__ __forceinline__ void red_add_v2h2(unsigned* p, uint2 v) {
    asm volatile("red.global.add.noftz.v2.f16x2 [%0], {%1,%2};"
                 :: "l"(p), "r"(v.x), "r"(v.y) : "memory");
}

__device__ __forceinline__ void pdl_begin() {
    cudaTriggerProgrammaticLaunchCompletion();
    cudaGridDependencySynchronize();
}

// ---------------- kernels ----------------

// zero deg_out (4 MB) -- main chain head
__global__ void k_zero_out() {
    pdl_begin();
    int i = blockIdx.x * blockDim.x + threadIdx.x;
    if (i < N_NODES / 4) ((int4*)g_deg_out)[i] = make_int4(0, 0, 0, 0);
}

// zero deg_in (4 MB) -- side stream head
__global__ void k_zero_in() {
    int i = blockIdx.x * blockDim.x + threadIdx.x;
    if (i < N_NODES / 4) ((int4*)g_deg_in)[i] = make_int4(0, 0, 0, 0);
}

// out-degrees only: 8 edges per thread (src array only)
__global__ void k_deg_out(const int* __restrict__ src) {
    pdl_begin();
    int i = blockIdx.x * blockDim.x + threadIdx.x;
    if (i >= N_EDGES / 8) return;
    int4 s0 = ((const int4*)src)[2 * i], s1 = ((const int4*)src)[2 * i + 1];
    atomicAdd(&g_deg_out[s0.x], 1); atomicAdd(&g_deg_out[s0.y], 1);
    atomicAdd(&g_deg_out[s0.z], 1); atomicAdd(&g_deg_out[s0.w], 1);
    atomicAdd(&g_deg_out[s1.x], 1); atomicAdd(&g_deg_out[s1.y], 1);
    atomicAdd(&g_deg_out[s1.z], 1); atomicAdd(&g_deg_out[s1.w], 1);
}

// in-degrees only: 8 edges per thread (dst array only) -- runs on side stream
__global__ void k_deg_in(const int* __restrict__ dst) {
    int i = blockIdx.x * blockDim.x + threadIdx.x;
    if (i >= N_EDGES / 8) return;
    int4 d0 = ((const int4*)dst)[2 * i], d1 = ((const int4*)dst)[2 * i + 1];
    atomicAdd(&g_deg_in[d0.x], 1); atomicAdd(&g_deg_in[d0.y], 1);
    atomicAdd(&g_deg_in[d0.z], 1); atomicAdd(&g_deg_in[d0.w], 1);
    atomicAdd(&g_deg_in[d1.x], 1); atomicAdd(&g_deg_in[d1.y], 1);
    atomicAdd(&g_deg_in[d1.z], 1); atomicAdd(&g_deg_in[d1.w], 1);
}

// x1 = (features * out_norm) @ W1, fp16-packed; also zeroes agg1 row (16B)
__global__ void k_proj1(const float* __restrict__ feat, const float* __restrict__ W1) {
    pdl_begin();
    __shared__ float sW[80];
    if (threadIdx.x < 80) sW[threadIdx.x] = W1[threadIdx.x];
    __syncthreads();
    int n = blockIdx.x * blockDim.x + threadIdx.x;
    if (n >= N_NODES) return;
    ((uint4*)g_agg1)[n] = make_uint4(0u, 0u, 0u, 0u);
    float onorm = rsqrtf(fmaxf((float)g_deg_out[n], 1.f));
    const float2* fp = (const float2*)(feat + (size_t)n * 10);
    float f[10];
#pragma unroll
    for (int i = 0; i < 5; i++) { float2 v = fp[i]; f[2*i] = v.x * onorm; f[2*i+1] = v.y * onorm; }
    float o[8];
#pragma unroll
    for (int j = 0; j < 8; j++) o[j] = 0.f;
#pragma unroll
    for (int i = 0; i < 10; i++)
#pragma unroll
        for (int j = 0; j < 8; j++) o[j] += f[i] * sW[i * 8 + j];
    g_x1h[n] = make_uint4(pack_h2(o[0], o[1]), pack_h2(o[2], o[3]),
                          pack_h2(o[4], o[5]), pack_h2(o[6], o[7]));
}

// agg1[dst] += x1h[src]  -- 4 edges/thread
__global__ void k_scatter1(const int* __restrict__ src, const int* __restrict__ dst) {
    pdl_begin();
    int i = blockIdx.x * blockDim.x + threadIdx.x;   // i < N_EDGES/4 (exact grid)
    int4 s = ((const int4*)src)[i];
    int4 d = ((const int4*)dst)[i];
    uint4 v0 = __ldg(&g_x1h[s.x]);
    uint4 v1 = __ldg(&g_x1h[s.y]);
    uint4 v2 = __ldg(&g_x1h[s.z]);
    uint4 v3 = __ldg(&g_x1h[s.w]);
    red_add_v4h2(&g_agg1[(size_t)d.x * 4], v0);
    red_add_v4h2(&g_agg1[(size_t)d.y * 4], v1);
    red_add_v4h2(&g_agg1[(size_t)d.z * 4], v2);
    red_add_v4h2(&g_agg1[(size_t)d.w * 4], v3);
}

// h1 = relu(fp32(agg1)*in_norm + b1); x2 = (h1*out_norm) @ W2 fp16-packed.
// Also zeroes agg2 + graph accumulators (consumed downstream).
__global__ void k_h1_proj2(const float* __restrict__ W2, const float* __restrict__ b1) {
    pdl_begin();
    __shared__ float sW[32], sb[8];
    if (threadIdx.x < 32) sW[threadIdx.x] = W2[threadIdx.x];
    if (threadIdx.x < 8)  sb[threadIdx.x] = b1[threadIdx.x];
    __syncthreads();
    int n = blockIdx.x * blockDim.x + threadIdx.x;
    if (n >= N_NODES) return;
    ((uint2*)g_agg2)[n] = make_uint2(0u, 0u);
    if (n < N_GRAPHS) { ((float4*)g_gsum)[n] = make_float4(0.f,0.f,0.f,0.f);
                        g_gcnt[n] = 0.f; }
    float innorm = rsqrtf(fmaxf((float)g_deg_in[n], 1.f));
    float onorm  = rsqrtf(fmaxf((float)g_deg_out[n], 1.f));
    uint4 raw = ((const uint4*)g_agg1)[n];
    float2 p0 = unpack_h2(raw.x), p1 = unpack_h2(raw.y);
    float2 p2 = unpack_h2(raw.z), p3 = unpack_h2(raw.w);
    float h[8] = { p0.x, p0.y, p1.x, p1.y, p2.x, p2.y, p3.x, p3.y };
#pragma unroll
    for (int j = 0; j < 8; j++) h[j] = fmaxf(h[j] * innorm + sb[j], 0.f);
    float o[4] = {0.f, 0.f, 0.f, 0.f};
#pragma unroll
    for (int j = 0; j < 8; j++)
#pragma unroll
        for (int k = 0; k < 4; k++) o[k] += h[j] * sW[j * 4 + k];
    g_x2h[n] = make_uint2(pack_h2(o[0] * onorm, o[1] * onorm),
                          pack_h2(o[2] * onorm, o[3] * onorm));
}

// agg2[dst] += x2h[src]  -- 4 edges/thread
__global__ void k_scatter2(const int* __restrict__ src, const int* __restrict__ dst) {
    pdl_begin();
    int i = blockIdx.x * blockDim.x + threadIdx.x;   // i < N_EDGES/4 (exact grid)
    int4 s = ((const int4*)src)[i];
    int4 d = ((const int4*)dst)[i];
    uint2 v0 = __ldg(&g_x2h[s.x]);
    uint2 v1 = __ldg(&g_x2h[s.y]);
    uint2 v2 = __ldg(&g_x2h[s.z]);
    uint2 v3 = __ldg(&g_x2h[s.w]);
    red_add_v2h2(&g_agg2[(size_t)d.x * 2], v0);
    red_add_v2h2(&g_agg2[(size_t)d.y * 2], v1);
    red_add_v2h2(&g_agg2[(size_t)d.z * 2], v2);
    red_add_v2h2(&g_agg2[(size_t)d.w * 2], v3);
}

// h2 = relu(fp32(agg2) * in_norm + b2); per-graph mean accumulation
__global__ void k_graph_reduce(const int* __restrict__ graph_ids, const float* __restrict__ b2) {
    pdl_begin();
    int n0 = blockIdx.x * blockDim.x + threadIdx.x;
    bool valid = (n0 < N_NODES);
    int n = valid ? n0 : (N_NODES - 1);
    uint2 raw = ((const uint2*)g_agg2)[n];
    float2 p0 = unpack_h2(raw.x), p1 = unpack_h2(raw.y);
    float innorm = rsqrtf(fmaxf((float)g_deg_in[n], 1.f));
    float h[4];
    h[0] = valid ? fmaxf(p0.x * innorm + __ldg(b2 + 0), 0.f) : 0.f;
    h[1] = valid ? fmaxf(p0.y * innorm + __ldg(b2 + 1), 0.f) : 0.f;
    h[2] = valid ? fmaxf(p1.x * innorm + __ldg(b2 + 2), 0.f) : 0.f;
    h[3] = valid ? fmaxf(p1.y * innorm + __ldg(b2 + 3), 0.f) : 0.f;
    float cnt = valid ? 1.f : 0.f;
    int gid = __ldg(graph_ids + n);

    unsigned full = 0xFFFFFFFFu;
    int g0 = __shfl_sync(full, gid, 0);
    bool uniform = __all_sync(full, gid == g0);
    int lane = threadIdx.x & 31;
    if (uniform) {
#pragma unroll
        for (int off = 16; off > 0; off >>= 1) {
#pragma unroll
            for (int k = 0; k < 4; k++) h[k] += __shfl_down_sync(full, h[k], off);
            cnt += __shfl_down_sync(full, cnt, off);
        }
        if (lane == 0) {
#pragma unroll
            for (int k = 0; k < 4; k++) atomicAdd(&g_gsum[g0 * 4 + k], h[k]);
            atomicAdd(&g_gcnt[g0], cnt);
        }
    } else if (valid) {
#pragma unroll
        for (int k = 0; k < 4; k++) atomicAdd(&g_gsum[gid * 4 + k], h[k]);
        atomicAdd(&g_gcnt[gid], 1.f);
    }
}

// out[g] = sigmoid(mean @ Wo + bo)
__global__ void k_final(const float* __restrict__ Wo, const float* __restrict__ bo,
                        float* __restrict__ out) {
    pdl_begin();
    int g = blockIdx.x * blockDim.x + threadIdx.x;
    if (g >= N_GRAPHS) return;
    float c = fmaxf(g_gcnt[g], 1.f);
    float z = __ldg(bo);
#pragma unroll
    for (int k = 0; k < 4; k++) z += (g_gsum[g * 4 + k] / c) * __ldg(Wo + k);
    out[g] = 1.f / (1.f + expf(-z));
}

// ---------------- launch ----------------
template <typename... Args>
static void launch_pdl(void (*kern)(Args...), int grid, int block, Args... args) {
    cudaLaunchConfig_t cfg = {};
    cfg.gridDim = dim3(grid, 1, 1);
    cfg.blockDim = dim3(block, 1, 1);
    cfg.stream = 0;
    cudaLaunchAttribute attr[1];
    attr[0].id = cudaLaunchAttributeProgrammaticStreamSerialization;
    attr[0].val.programmaticStreamSerializationAllowed = 1;
    cfg.attrs = attr;
    cfg.numAttrs = 1;
    cudaLaunchKernelEx(&cfg, kern, args...);
}

extern "C" void kernel_launch(void* const* d_in, const int* in_sizes, int n_in,
                              void* d_out, int out_size) {
    const float* feat      = (const float*)d_in[0];
    const int*   src       = (const int*)d_in[1];
    const int*   dst       = (const int*)d_in[2];
    const int*   graph_ids = (const int*)d_in[3];
    const float* W1        = (const float*)d_in[4];
    const float* b1        = (const float*)d_in[5];
    const float* W2        = (const float*)d_in[6];
    const float* b2        = (const float*)d_in[7];
    const float* Wo        = (const float*)d_in[8];
    const float* bo        = (const float*)d_in[9];
    float* out = (float*)d_out;

    // Side stream + events (host objects only — no device memory). Created per
    // call; kernel_launch only runs a handful of times (correctness + capture).
    cudaStream_t s2;
    cudaStreamCreateWithFlags(&s2, cudaStreamNonBlocking);
    cudaEvent_t evFork, evJoin;
    cudaEventCreateWithFlags(&evFork, cudaEventDisableTiming);
    cudaEventCreateWithFlags(&evJoin, cudaEventDisableTiming);

    const int T = 256;
    const int gE8 = (N_EDGES / 8 + T - 1) / T;

    // main chain head
    launch_pdl(k_zero_out, (N_NODES / 4 + T - 1) / T, T);

    // fork: deg_in runs concurrently on s2 (joined before k_h1_proj2)
    cudaEventRecord(evFork, 0);
    cudaStreamWaitEvent(s2, evFork, 0);
    k_zero_in<<<(N_NODES / 4 + T - 1) / T, T, 0, s2>>>();
    k_deg_in<<<gE8, T, 0, s2>>>(dst);
    cudaEventRecord(evJoin, s2);

    // main chain
    launch_pdl(k_deg_out, gE8, T, src);
    launch_pdl(k_proj1, (N_NODES + T - 1) / T, T, feat, W1);
    launch_pdl(k_scatter1, (N_EDGES / 4) / T, T, src, dst);
    cudaStreamWaitEvent(0, evJoin, 0);
    launch_pdl(k_h1_proj2, (N_NODES + T - 1) / T, T, W2, b1);
    launch_pdl(k_scatter2, (N_EDGES / 4) / T, T, src, dst);
    launch_pdl(k_graph_reduce, (N_NODES + T - 1) / T, T, graph_ids, b2);
    launch_pdl(k_final, (N_GRAPHS + T - 1) / T, T, Wo, bo, out);
}

// round 13
// speedup vs baseline: 1.4111x; 1.0036x over previous
#include <cuda_runtime.h>
#include <cuda_fp16.h>
#include <math.h>

#define N_NODES  1000000
#define N_EDGES  16000000
#define N_GRAPHS 1024

// ---------------- scratch (device globals: allocation-free) ----------------
__device__ __align__(16) uint4    g_y1h[N_NODES];       // y1 = f@W1 (no norm): 1M x 8 fp16
__device__ __align__(16) uint4    g_x1h[N_NODES];       // x1 = y1*onorm: 1M x 8 fp16
__device__ __align__(16) uint2    g_x2h[N_NODES];       // x2: 1M x 4 fp16
__device__ __align__(16) unsigned g_agg1[N_NODES * 4];  // agg1: 1M x 8 fp16
__device__ __align__(16) unsigned g_agg2[N_NODES * 2];  // agg2: 1M x 4 fp16
__device__ __align__(16) int      g_deg_out[N_NODES];
__device__ __align__(16) int      g_deg_in[N_NODES];
__device__ float g_gsum[N_GRAPHS * 4];
__device__ float g_gcnt[N_GRAPHS];

__device__ __forceinline__ unsigned pack_h2(float x, float y) {
    __half2 h = __float22half2_rn(make_float2(x, y));
    return *reinterpret_cast<unsigned*>(&h);
}
__device__ __forceinline__ float2 unpack_h2(unsigned u) {
    __half2 h = *reinterpret_cast<__half2*>(&u);
    return __half22float2(h);
}
__device__ __forceinline__ unsigned mul_h2(unsigned u, __half2 s) {
    __half2 h = *reinterpret_cast<__half2*>(&u);
    h = __hmul2(h, s);
    return *reinterpret_cast<unsigned*>(&h);
}

__device__ __forceinline__ void red_add_v4h2(unsigned* p, uint4 v) {
    asm volatile("red.global.add.noftz.v4.f16x2 [%0], {%1,%2,%3,%4};"
                 :: "l"(p), "r"(v.x), "r"(v.y), "r"(v.z), "r"(v.w) : "memory");
}
__device__ __forceinline__ void red_add_v2h2(unsigned* p, uint2 v) {
    asm volatile("red.global.add.noftz.v2.f16x2 [%0], {%1,%2};"
                 :: "l"(p), "r"(v.x), "r"(v.y) : "memory");
}

__device__ __forceinline__ void pdl_begin() {
    cudaTriggerProgrammaticLaunchCompletion();
    cudaGridDependencySynchronize();
}

// ---------------- kernels ----------------

// zero both degree arrays (deg_in is accumulated inside scatter1)
__global__ void k_zero() {
    pdl_begin();
    int i = blockIdx.x * blockDim.x + threadIdx.x;
    if (i < N_NODES / 4) { ((int4*)g_deg_out)[i] = make_int4(0, 0, 0, 0);
                           ((int4*)g_deg_in)[i]  = make_int4(0, 0, 0, 0); }
}

// out-degrees: 8 edges per thread
__global__ void k_deg_out(const int* __restrict__ src) {
    pdl_begin();
    int i = blockIdx.x * blockDim.x + threadIdx.x;
    if (i >= N_EDGES / 8) return;
    int4 s0 = ((const int4*)src)[2 * i], s1 = ((const int4*)src)[2 * i + 1];
    atomicAdd(&g_deg_out[s0.x], 1); atomicAdd(&g_deg_out[s0.y], 1);
    atomicAdd(&g_deg_out[s0.z], 1); atomicAdd(&g_deg_out[s0.w], 1);
    atomicAdd(&g_deg_out[s1.x], 1); atomicAdd(&g_deg_out[s1.y], 1);
    atomicAdd(&g_deg_out[s1.z], 1); atomicAdd(&g_deg_out[s1.w], 1);
}

// y1 = f @ W1 (NO norm) -- needs no degrees; runs on side stream from t=0
__global__ void k_proj1a(const float* __restrict__ feat, const float* __restrict__ W1) {
    __shared__ float sW[80];
    if (threadIdx.x < 80) sW[threadIdx.x] = W1[threadIdx.x];
    __syncthreads();
    int n = blockIdx.x * blockDim.x + threadIdx.x;
    if (n >= N_NODES) return;
    const float2* fp = (const float2*)(feat + (size_t)n * 10);
    float f[10];
#pragma unroll
    for (int i = 0; i < 5; i++) { float2 v = fp[i]; f[2*i] = v.x; f[2*i+1] = v.y; }
    float o[8];
#pragma unroll
    for (int j = 0; j < 8; j++) o[j] = 0.f;
#pragma unroll
    for (int i = 0; i < 10; i++)
#pragma unroll
        for (int j = 0; j < 8; j++) o[j] += f[i] * sW[i * 8 + j];
    g_y1h[n] = make_uint4(pack_h2(o[0], o[1]), pack_h2(o[2], o[3]),
                          pack_h2(o[4], o[5]), pack_h2(o[6], o[7]));
}

// x1 = y1 * out_norm (half2 multiplies); also zeroes agg1 row
__global__ void k_proj1b() {
    pdl_begin();
    int n = blockIdx.x * blockDim.x + threadIdx.x;
    if (n >= N_NODES) return;
    ((uint4*)g_agg1)[n] = make_uint4(0u, 0u, 0u, 0u);
    float onf = rsqrtf(fmaxf((float)g_deg_out[n], 1.f));
    __half2 on = __float2half2_rn(onf);
    uint4 y = g_y1h[n];
    g_x1h[n] = make_uint4(mul_h2(y.x, on), mul_h2(y.y, on),
                          mul_h2(y.z, on), mul_h2(y.w, on));
}

// agg1[dst] += x1h[src]; ALSO accumulates deg_in (dst already loaded here)
__global__ void k_scatter1(const int* __restrict__ src, const int* __restrict__ dst) {
    pdl_begin();
    int i = blockIdx.x * blockDim.x + threadIdx.x;   // i < N_EDGES/4 (exact grid)
    int4 s = ((const int4*)src)[i];
    int4 d = ((const int4*)dst)[i];
    uint4 v0 = __ldg(&g_x1h[s.x]);
    uint4 v1 = __ldg(&g_x1h[s.y]);
    uint4 v2 = __ldg(&g_x1h[s.z]);
    uint4 v3 = __ldg(&g_x1h[s.w]);
    red_add_v4h2(&g_agg1[(size_t)d.x * 4], v0);
    red_add_v4h2(&g_agg1[(size_t)d.y * 4], v1);
    red_add_v4h2(&g_agg1[(size_t)d.z * 4], v2);
    red_add_v4h2(&g_agg1[(size_t)d.w * 4], v3);
    atomicAdd(&g_deg_in[d.x], 1);
    atomicAdd(&g_deg_in[d.y], 1);
    atomicAdd(&g_deg_in[d.z], 1);
    atomicAdd(&g_deg_in[d.w], 1);
}

// h1 = relu(fp32(agg1)*in_norm + b1); x2 = (h1*out_norm) @ W2 fp16-packed.
// Also zeroes agg2 + graph accumulators.
__global__ void k_h1_proj2(const float* __restrict__ W2, const float* __restrict__ b1) {
    pdl_begin();
    __shared__ float sW[32], sb[8];
    if (threadIdx.x < 32) sW[threadIdx.x] = W2[threadIdx.x];
    if (threadIdx.x < 8)  sb[threadIdx.x] = b1[threadIdx.x];
    __syncthreads();
    int n = blockIdx.x * blockDim.x + threadIdx.x;
    if (n >= N_NODES) return;
    ((uint2*)g_agg2)[n] = make_uint2(0u, 0u);
    if (n < N_GRAPHS) { ((float4*)g_gsum)[n] = make_float4(0.f,0.f,0.f,0.f);
                        g_gcnt[n] = 0.f; }
    float innorm = rsqrtf(fmaxf((float)g_deg_in[n], 1.f));
    float onorm  = rsqrtf(fmaxf((float)g_deg_out[n], 1.f));
    uint4 raw = ((const uint4*)g_agg1)[n];
    float2 p0 = unpack_h2(raw.x), p1 = unpack_h2(raw.y);
    float2 p2 = unpack_h2(raw.z), p3 = unpack_h2(raw.w);
    float h[8] = { p0.x, p0.y, p1.x, p1.y, p2.x, p2.y, p3.x, p3.y };
#pragma unroll
    for (int j = 0; j < 8; j++) h[j] = fmaxf(h[j] * innorm + sb[j], 0.f);
    float o[4] = {0.f, 0.f, 0.f, 0.f};
#pragma unroll
    for (int j = 0; j < 8; j++)
#pragma unroll
        for (int k = 0; k < 4; k++) o[k] += h[j] * sW[j * 4 + k];
    g_x2h[n] = make_uint2(pack_h2(o[0] * onorm, o[1] * onorm),
                          pack_h2(o[2] * onorm, o[3] * onorm));
}

// agg2[dst] += x2h[src]  -- 4 edges/thread
__global__ void k_scatter2(const int* __restrict__ src, const int* __restrict__ dst) {
    pdl_begin();
    int i = blockIdx.x * blockDim.x + threadIdx.x;   // i < N_EDGES/4 (exact grid)
    int4 s = ((const int4*)src)[i];
    int4 d = ((const int4*)dst)[i];
    uint2 v0 = __ldg(&g_x2h[s.x]);
    uint2 v1 = __ldg(&g_x2h[s.y]);
    uint2 v2 = __ldg(&g_x2h[s.z]);
    uint2 v3 = __ldg(&g_x2h[s.w]);
    red_add_v2h2(&g_agg2[(size_t)d.x * 2], v0);
    red_add_v2h2(&g_agg2[(size_t)d.y * 2], v1);
    red_add_v2h2(&g_agg2[(size_t)d.z * 2], v2);
    red_add_v2h2(&g_agg2[(size_t)d.w * 2], v3);
}

// h2 = relu(fp32(agg2) * in_norm + b2); per-graph mean accumulation
__global__ void k_graph_reduce(const int* __restrict__ graph_ids, const float* __restrict__ b2) {
    pdl_begin();
    int n0 = blockIdx.x * blockDim.x + threadIdx.x;
    bool valid = (n0 < N_NODES);
    int n = valid ? n0 : (N_NODES - 1);
    uint2 raw = ((const uint2*)g_agg2)[n];
    float2 p0 = unpack_h2(raw.x), p1 = unpack_h2(raw.y);
    float innorm = rsqrtf(fmaxf((float)g_deg_in[n], 1.f));
    float h[4];
    h[0] = valid ? fmaxf(p0.x * innorm + __ldg(b2 + 0), 0.f) : 0.f;
    h[1] = valid ? fmaxf(p0.y * innorm + __ldg(b2 + 1), 0.f) : 0.f;
    h[2] = valid ? fmaxf(p1.x * innorm + __ldg(b2 + 2), 0.f) : 0.f;
    h[3] = valid ? fmaxf(p1.y * innorm + __ldg(b2 + 3), 0.f) : 0.f;
    float cnt = valid ? 1.f : 0.f;
    int gid = __ldg(graph_ids + n);

    unsigned full = 0xFFFFFFFFu;
    int g0 = __shfl_sync(full, gid, 0);
    bool uniform = __all_sync(full, gid == g0);
    int lane = threadIdx.x & 31;
    if (uniform) {
#pragma unroll
        for (int off = 16; off > 0; off >>= 1) {
#pragma unroll
            for (int k = 0; k < 4; k++) h[k] += __shfl_down_sync(full, h[k], off);
            cnt += __shfl_down_sync(full, cnt, off);
        }
        if (lane == 0) {
#pragma unroll
            for (int k = 0; k < 4; k++) atomicAdd(&g_gsum[g0 * 4 + k], h[k]);
            atomicAdd(&g_gcnt[g0], cnt);
        }
    } else if (valid) {
#pragma unroll
        for (int k = 0; k < 4; k++) atomicAdd(&g_gsum[gid * 4 + k], h[k]);
        atomicAdd(&g_gcnt[gid], 1.f);
    }
}

// out[g] = sigmoid(mean @ Wo + bo)
__global__ void k_final(const float* __restrict__ Wo, const float* __restrict__ bo,
                        float* __restrict__ out) {
    pdl_begin();
    int g = blockIdx.x * blockDim.x + threadIdx.x;
    if (g >= N_GRAPHS) return;
    float c = fmaxf(g_gcnt[g], 1.f);
    float z = __ldg(bo);
#pragma unroll
    for (int k = 0; k < 4; k++) z += (g_gsum[g * 4 + k] / c) * __ldg(Wo + k);
    out[g] = 1.f / (1.f + expf(-z));
}

// ---------------- launch ----------------
template <typename... Args>
static void launch_pdl(void (*kern)(Args...), int grid, int block, Args... args) {
    cudaLaunchConfig_t cfg = {};
    cfg.gridDim = dim3(grid, 1, 1);
    cfg.blockDim = dim3(block, 1, 1);
    cfg.stream = 0;
    cudaLaunchAttribute attr[1];
    attr[0].id = cudaLaunchAttributeProgrammaticStreamSerialization;
    attr[0].val.programmaticStreamSerializationAllowed = 1;
    cfg.attrs = attr;
    cfg.numAttrs = 1;
    cudaLaunchKernelEx(&cfg, kern, args...);
}

extern "C" void kernel_launch(void* const* d_in, const int* in_sizes, int n_in,
                              void* d_out, int out_size) {
    const float* feat      = (const float*)d_in[0];
    const int*   src       = (const int*)d_in[1];
    const int*   dst       = (const int*)d_in[2];
    const int*   graph_ids = (const int*)d_in[3];
    const float* W1        = (const float*)d_in[4];
    const float* b1        = (const float*)d_in[5];
    const float* W2        = (const float*)d_in[6];
    const float* b2        = (const float*)d_in[7];
    const float* Wo        = (const float*)d_in[8];
    const float* bo        = (const float*)d_in[9];
    float* out = (float*)d_out;

    // Side stream carries only the degree-independent GEMM (DRAM-bound),
    // genuinely overlapping the L2-op-bound deg_out on the main stream.
    cudaStream_t s2;
    cudaStreamCreateWithFlags(&s2, cudaStreamNonBlocking);
    cudaEvent_t evFork, evJoin;
    cudaEventCreateWithFlags(&evFork, cudaEventDisableTiming);
    cudaEventCreateWithFlags(&evJoin, cudaEventDisableTiming);

    const int T = 256;
    const int gN = (N_NODES + T - 1) / T;

    cudaEventRecord(evFork, 0);
    cudaStreamWaitEvent(s2, evFork, 0);
    k_proj1a<<<gN, T, 0, s2>>>(feat, W1);
    cudaEventRecord(evJoin, s2);

    launch_pdl(k_zero, (N_NODES / 4 + T - 1) / T, T);
    launch_pdl(k_deg_out, (N_EDGES / 8 + T - 1) / T, T, src);
    cudaStreamWaitEvent(0, evJoin, 0);
    launch_pdl(k_proj1b, gN, T);
    launch_pdl(k_scatter1, (N_EDGES / 4) / T, T, src, dst);
    launch_pdl(k_h1_proj2, gN, T, W2, b1);
    launch_pdl(k_scatter2, (N_EDGES / 4) / T, T, src, dst);
    launch_pdl(k_graph_reduce, gN, T, graph_ids, b2);
    launch_pdl(k_final, (N_GRAPHS + T - 1) / T, T, Wo, bo, out);
}